// round 14
// baseline (speedup 1.0000x reference)
#include <cuda_runtime.h>
#include <cuda_fp16.h>
#include <stdint.h>

#define N_NODES 10000
#define N_EDGES 160000
#define M_PAD   10112           // 79 * 128
#define SPLIT_M 5120            // 40 tiles chain A, 39 chain B

// ---------------- device scratch (no allocations allowed) ----------------
__device__ __half g_xh  [N_NODES * 256];  // x, fp16
__device__ __half g_aggx[M_PAD * 256];    // ÂX, fp16
__device__ __half g_h1  [M_PAD * 512];    // layer-1 out, fp16
__device__ __half g_xw2 [N_NODES * 256];  // h1 @ W2, fp16
__device__ __half g_w1t [512 * 256];      // W1^T, fp16
__device__ __half g_w2t [256 * 512];      // W2^T, fp16
__device__ float g_dinv[N_NODES];
__device__ int   g_cnt[N_NODES];          // zero at load; scan self-clears
__device__ int   g_off[N_NODES + 1];
__device__ int   g_cur[N_NODES];
__device__ int   g_csr[N_EDGES];

// ---------------- PTX helpers ----------------
__device__ __forceinline__ uint32_t smem_to_u32(const void* p) {
    uint32_t a;
    asm("{ .reg .u64 t; cvta.to.shared.u64 t, %1; cvt.u32.u64 %0, t; }" : "=r"(a) : "l"(p));
    return a;
}
__device__ __forceinline__ void cp_async16(uint32_t dst, const void* src) {
    asm volatile("cp.async.cg.shared.global [%0], [%1], 16;" :: "r"(dst), "l"(src));
}
#define CP_COMMIT()  asm volatile("cp.async.commit_group;" ::: "memory")
#define CP_WAIT(n)   asm volatile("cp.async.wait_group %0;" :: "n"(n) : "memory")

__device__ __forceinline__ void mma_f16(float* d, const uint32_t* a, const uint32_t* b) {
    asm volatile(
        "mma.sync.aligned.m16n8k16.row.col.f32.f16.f16.f32 "
        "{%0,%1,%2,%3},{%4,%5,%6,%7},{%8,%9},{%0,%1,%2,%3};"
        : "+f"(d[0]), "+f"(d[1]), "+f"(d[2]), "+f"(d[3])
        : "r"(a[0]), "r"(a[1]), "r"(a[2]), "r"(a[3]), "r"(b[0]), "r"(b[1]));
}

// ---------------- threefry2x32 (JAX-compatible, validated) ----------------
#define TF_ROUND(v0, v1, r) do { (v0) += (v1); (v1) = ((v1) << (r)) | ((v1) >> (32 - (r))); (v1) ^= (v0); } while (0)
__host__ __device__ __forceinline__ void tf2x32(unsigned k0, unsigned k1,
                                                unsigned x0, unsigned x1,
                                                unsigned& o0, unsigned& o1) {
    unsigned ks0 = k0, ks1 = k1, ks2 = k0 ^ k1 ^ 0x1BD11BDAu;
    unsigned v0 = x0 + ks0, v1 = x1 + ks1;
    TF_ROUND(v0, v1, 13); TF_ROUND(v0, v1, 15); TF_ROUND(v0, v1, 26); TF_ROUND(v0, v1, 6);
    v0 += ks1; v1 += ks2 + 1u;
    TF_ROUND(v0, v1, 17); TF_ROUND(v0, v1, 29); TF_ROUND(v0, v1, 16); TF_ROUND(v0, v1, 24);
    v0 += ks2; v1 += ks0 + 2u;
    TF_ROUND(v0, v1, 13); TF_ROUND(v0, v1, 15); TF_ROUND(v0, v1, 26); TF_ROUND(v0, v1, 6);
    v0 += ks0; v1 += ks1 + 3u;
    TF_ROUND(v0, v1, 17); TF_ROUND(v0, v1, 29); TF_ROUND(v0, v1, 16); TF_ROUND(v0, v1, 24);
    v0 += ks1; v1 += ks2 + 4u;
    TF_ROUND(v0, v1, 13); TF_ROUND(v0, v1, 15); TF_ROUND(v0, v1, 26); TF_ROUND(v0, v1, 6);
    v0 += ks2; v1 += ks0 + 5u;
    o0 = v0; o1 = v1;
}
// dropout keep decision for element index i (bit31 test == u < 0.5, validated)
__device__ __forceinline__ bool tf_keep(unsigned k0, unsigned k1, unsigned i) {
    unsigned y0, y1;
    tf2x32(k0, k1, 0u, i, y0, y1);
    return ((y0 ^ y1) >> 31) == 0u;
}

// ---------------- preprocessing --------------------------------------------
// ILP-5 count: 125 blocks x 256 threads x 5 edges = exactly 160000.
__global__ void count_kernel(const void* __restrict__ ei) {
    int e0 = (blockIdx.x * blockDim.x + threadIdx.x) * 5;
    const unsigned* u = (const unsigned*)ei;
    unsigned hior = 0;
#pragma unroll
    for (int j = 0; j < 5; j++) hior |= u[2u * (unsigned)(e0 + j) + 1u];
    bool is64 = !__any_sync(0xffffffffu, hior != 0u);
    int d[5];
    if (is64) {
        const long long* p = (const long long*)ei + N_EDGES + e0;
#pragma unroll
        for (int j = 0; j < 5; j++) d[j] = (int)p[j];
    } else {
        const int* p = (const int*)ei + N_EDGES + e0;
#pragma unroll
        for (int j = 0; j < 5; j++) d[j] = p[j];
    }
#pragma unroll
    for (int j = 0; j < 5; j++) atomicAdd(&g_cnt[d[j]], 1);
}

// one-pass scan: 1024 threads x 10 elements, 3 barriers total
__global__ void scan_kernel() {
    __shared__ int warp_pre[32];
    const int t = threadIdx.x;
    const int lane = t & 31, wid = t >> 5;
    const int base = t * 10;
    int v[10];
    int sum = 0;
#pragma unroll
    for (int j = 0; j < 10; j++) {
        int i = base + j;
        int c = (i < N_NODES) ? g_cnt[i] : 0;
        v[j] = c;
        sum += c;
        if (i < N_NODES) {
            g_dinv[i] = rsqrtf((float)(c + 1));
            g_cnt[i] = 0;                       // self-clear for graph replay
        }
    }
    int incl = sum;
#pragma unroll
    for (int o = 1; o < 32; o <<= 1) {
        int x = __shfl_up_sync(0xffffffffu, incl, o);
        if (lane >= o) incl += x;
    }
    if (lane == 31) warp_pre[wid] = incl;
    __syncthreads();
    if (wid == 0) {
        int ws = warp_pre[lane];
        int wincl = ws;
#pragma unroll
        for (int o = 1; o < 32; o <<= 1) {
            int x = __shfl_up_sync(0xffffffffu, wincl, o);
            if (lane >= o) wincl += x;
        }
        warp_pre[lane] = wincl - ws;
    }
    __syncthreads();
    int excl = incl - sum + warp_pre[wid];
#pragma unroll
    for (int j = 0; j < 10; j++) {
        int i = base + j;
        if (i < N_NODES) {
            g_off[i] = excl;
            g_cur[i] = excl;
        }
        excl += v[j];
    }
    if (base + 10 >= N_NODES && base < N_NODES) g_off[N_NODES] = excl;
}

// ILP-5 fill (same exact-coverage grid as count)
__global__ void fill_kernel(const void* __restrict__ ei) {
    int e0 = (blockIdx.x * blockDim.x + threadIdx.x) * 5;
    const unsigned* u = (const unsigned*)ei;
    unsigned hior = 0;
#pragma unroll
    for (int j = 0; j < 5; j++) hior |= u[2u * (unsigned)(e0 + j) + 1u];
    bool is64 = !__any_sync(0xffffffffu, hior != 0u);
    int s[5], d[5];
    if (is64) {
        const long long* ps = (const long long*)ei + e0;
        const long long* pd = (const long long*)ei + N_EDGES + e0;
#pragma unroll
        for (int j = 0; j < 5; j++) { s[j] = (int)ps[j]; d[j] = (int)pd[j]; }
    } else {
        const int* ps = (const int*)ei + e0;
        const int* pd = (const int*)ei + N_EDGES + e0;
#pragma unroll
        for (int j = 0; j < 5; j++) { s[j] = ps[j]; d[j] = pd[j]; }
    }
#pragma unroll
    for (int j = 0; j < 5; j++)
        g_csr[atomicAdd(&g_cur[d[j]], 1)] = s[j];
}

// x -> fp16 (vectorized)
__global__ void xh_kernel(const float* __restrict__ x) {
    int i = blockIdx.x * blockDim.x + threadIdx.x;   // float4 index
    float4 v = ((const float4*)x)[i];
    __half2 h0 = __floats2half2_rn(v.x, v.y);
    __half2 h1 = __floats2half2_rn(v.z, v.w);
    ((uint2*)g_xh)[i] = make_uint2(*(uint32_t*)&h0, *(uint32_t*)&h1);
}

// two transposes -> fp16
__global__ void transpose2_kernel(const float* __restrict__ W1,
                                  const float* __restrict__ W2) {
    __shared__ float tile[32][33];
    int z = blockIdx.z;
    const float* src = (z == 0) ? W1 : W2;
    __half* dst = (z == 0) ? g_w1t : g_w2t;
    int R = (z == 0) ? 256 : 512;
    int C = (z == 0) ? 512 : 256;
    if (blockIdx.x * 32 >= C || blockIdx.y * 32 >= R) return;
    int c0 = blockIdx.x * 32, r0 = blockIdx.y * 32;
#pragma unroll
    for (int i = 0; i < 32; i += 8) {
        int r = r0 + threadIdx.y + i, c = c0 + threadIdx.x;
        tile[threadIdx.y + i][threadIdx.x] = src[(size_t)r * C + c];
    }
    __syncthreads();
#pragma unroll
    for (int i = 0; i < 32; i += 8) {
        int c = c0 + threadIdx.y + i, r = r0 + threadIdx.x;
        dst[(size_t)c * R + r] = __float2half(tile[threadIdx.x][threadIdx.y + i]);
    }
}

// ---------------- fp16 tensor-core GEMM -------------------------------------
// EPI 0: plain fp16 store. EPI 1: bias+relu+INLINE threefry dropout, fp16 store.
#define SROW32 36
#define S_BUF32 (256 * SROW32)

template <int N_OUT, int K_TOT, int EPI>
__global__ void __launch_bounds__(256, 2)
hgemm_kernel(const __half* __restrict__ A, const __half* __restrict__ Bt,
             __half* __restrict__ C, const float* __restrict__ bias,
             unsigned mk0, unsigned mk1, int M, int m0)
{
    extern __shared__ uint32_t sm32[];
    const int tid = threadIdx.x;
    const int wid = tid >> 5, lane = tid & 31;
    const int g = lane >> 2, tig = lane & 3;
    const int wm = wid >> 1, wn = wid & 1;
    const int bm = m0 + blockIdx.y * 128;
    const int bn = blockIdx.x * 128;
    constexpr int NBK = K_TOT / 64;

    const uint32_t sbase = smem_to_u32(sm32);

    float acc[2][8][4];
#pragma unroll
    for (int mi = 0; mi < 2; mi++)
#pragma unroll
        for (int ni = 0; ni < 8; ni++)
#pragma unroll
            for (int j = 0; j < 4; j++) acc[mi][ni][j] = 0.0f;

    auto load_tile = [&](int kc, int buf) {
#pragma unroll
        for (int r = 0; r < 4; r++) {
            int chunk = r * 256 + tid;
            int row = chunk >> 3;
            int f4  = chunk & 7;
            int gr = bm + row; if (gr >= M) gr = M - 1;
            uint32_t dA = sbase + (uint32_t)(buf * S_BUF32 + row * SROW32 + f4 * 4) * 4u;
            cp_async16(dA, A + (size_t)gr * K_TOT + kc * 64 + f4 * 8);
            int gn = bn + row;
            uint32_t dB = sbase + (uint32_t)(buf * S_BUF32 + (128 + row) * SROW32 + f4 * 4) * 4u;
            cp_async16(dB, Bt + (size_t)gn * K_TOT + kc * 64 + f4 * 8);
        }
    };

    load_tile(0, 0);
    CP_COMMIT();

    for (int kc = 0; kc < NBK; kc++) {
        int buf = kc & 1;
        if (kc + 1 < NBK) {
            load_tile(kc + 1, buf ^ 1);
            CP_COMMIT();
            CP_WAIT(1);
        } else {
            CP_WAIT(0);
        }
        __syncthreads();

        const uint32_t* As = sm32 + buf * S_BUF32;
        const uint32_t* Bs = As + 128 * SROW32;
        const int rm = wm * 32;
        const int cn = wn * 64;

#pragma unroll
        for (int s = 0; s < 4; s++) {
            int k0u = s * 8;
            uint32_t af[2][4];
#pragma unroll
            for (int mi = 0; mi < 2; mi++) {
                int r0 = rm + mi * 16 + g;
                af[mi][0] = As[r0 * SROW32 + k0u + tig];
                af[mi][1] = As[(r0 + 8) * SROW32 + k0u + tig];
                af[mi][2] = As[r0 * SROW32 + k0u + 4 + tig];
                af[mi][3] = As[(r0 + 8) * SROW32 + k0u + 4 + tig];
            }
#pragma unroll
            for (int ni = 0; ni < 8; ni++) {
                int n0 = cn + ni * 8 + g;
                uint32_t bf[2];
                bf[0] = Bs[n0 * SROW32 + k0u + tig];
                bf[1] = Bs[n0 * SROW32 + k0u + 4 + tig];
                mma_f16(acc[0][ni], af[0], bf);
                mma_f16(acc[1][ni], af[1], bf);
            }
        }
        __syncthreads();
    }

#pragma unroll
    for (int mi = 0; mi < 2; mi++) {
#pragma unroll
        for (int h = 0; h < 2; h++) {
            int m = bm + wm * 32 + mi * 16 + g + h * 8;
            if (m >= M) continue;
#pragma unroll
            for (int ni = 0; ni < 8; ni++) {
                int n0 = bn + wn * 64 + ni * 8 + tig * 2;
                float v0 = acc[mi][ni][h * 2 + 0];
                float v1 = acc[mi][ni][h * 2 + 1];
                if (EPI == 0) {
                    *(__half2*)(C + (size_t)m * N_OUT + n0) = __floats2half2_rn(v0, v1);
                } else {
                    float r0v = fmaxf(v0 + bias[n0], 0.0f);
                    float r1v = fmaxf(v1 + bias[n0 + 1], 0.0f);
                    unsigned idx = (unsigned)m * (unsigned)N_OUT + (unsigned)n0;
                    r0v = tf_keep(mk0, mk1, idx)      ? r0v * 2.0f : 0.0f;
                    r1v = tf_keep(mk0, mk1, idx + 1u) ? r1v * 2.0f : 0.0f;
                    *(__half2*)(C + (size_t)m * N_OUT + n0) = __floats2half2_rn(r0v, r1v);
                }
            }
        }
    }
}

// ---------------- aggregations (half2 gathers) -------------------------------
__global__ void aggx_kernel(int base) {
    int n = base + blockIdx.x, c2 = threadIdx.x;
    float dn = g_dinv[n];
    float2 hv = __half22float2(((const __half2*)(g_xh + (size_t)n * 256))[c2]);
    float a0 = dn * hv.x, a1 = dn * hv.y;
    int k0 = g_off[n], k1 = g_off[n + 1];
    for (int k = k0; k < k1; k++) {
        int s = g_csr[k];
        float ds = g_dinv[s];
        float2 sv = __half22float2(((const __half2*)(g_xh + (size_t)s * 256))[c2]);
        a0 += ds * sv.x;
        a1 += ds * sv.y;
    }
    ((__half2*)(g_aggx + (size_t)n * 256))[c2] = __floats2half2_rn(a0 * dn, a1 * dn);
}

// agg2: gather + bias + relu + INLINE threefry dropout (R5-R7 proven pattern)
__global__ void agg2_kernel(const __half* __restrict__ xw,
                            const float* __restrict__ bias,
                            float* __restrict__ out,
                            unsigned dk0, unsigned dk1) {
    int n = blockIdx.x, c2 = threadIdx.x;
    float dn = g_dinv[n];
    float2 hv = __half22float2(((const __half2*)(xw + (size_t)n * 256))[c2]);
    float a0 = dn * hv.x, a1 = dn * hv.y;
    int k0 = g_off[n], k1 = g_off[n + 1];
    for (int k = k0; k < k1; k++) {
        int s = g_csr[k];
        float ds = g_dinv[s];
        float2 sv = __half22float2(((const __half2*)(xw + (size_t)s * 256))[c2]);
        a0 += ds * sv.x;
        a1 += ds * sv.y;
    }
    int c = c2 * 2;
    float v0 = fmaxf(a0 * dn + bias[c], 0.0f);
    float v1 = fmaxf(a1 * dn + bias[c + 1], 0.0f);
    unsigned i = (unsigned)(n * 256 + c);
    out[i]     = tf_keep(dk0, dk1, i)      ? v0 * 2.0f : 0.0f;
    out[i + 1] = tf_keep(dk0, dk1, i + 1u) ? v1 * 2.0f : 0.0f;
}

// ---------------- launch (R9/R13 topology, no mask kernels) -------------------
extern "C" void kernel_launch(void* const* d_in, const int* in_sizes, int n_in,
                              void* d_out, int out_size)
{
    const float* x  = (const float*)d_in[0];
    const void*  ei = d_in[1];
    const float* W1 = (const float*)d_in[2];
    const float* b1 = (const float*)d_in[3];
    const float* W2 = (const float*)d_in[4];
    const float* b2 = (const float*)d_in[5];
    float* out = (float*)d_out;

    __half *p_aggx, *p_h1, *p_xw2, *p_w1t, *p_w2t;
    cudaGetSymbolAddress((void**)&p_aggx, g_aggx);
    cudaGetSymbolAddress((void**)&p_h1,   g_h1);
    cudaGetSymbolAddress((void**)&p_xw2,  g_xw2);
    cudaGetSymbolAddress((void**)&p_w1t,  g_w1t);
    cudaGetSymbolAddress((void**)&p_w2t,  g_w2t);

    constexpr int SMEMB = 2 * S_BUF32 * 4;
    cudaFuncSetAttribute(hgemm_kernel<512, 256, 1>,
                         cudaFuncAttributeMaxDynamicSharedMemorySize, SMEMB);
    cudaFuncSetAttribute(hgemm_kernel<256, 512, 0>,
                         cudaFuncAttributeMaxDynamicSharedMemorySize, SMEMB);

    unsigned dk1_0, dk1_1, dk2_0, dk2_1;
    tf2x32(0u, 42u, 0u, 0u, dk1_0, dk1_1);
    tf2x32(0u, 42u, 0u, 1u, dk2_0, dk2_1);

    static cudaStream_t s1 = nullptr, s2 = nullptr;
    static cudaEvent_t ev_fork = nullptr, ev_join = nullptr, ev_fill = nullptr,
                       ev_b1 = nullptr, ev_xh = nullptr;
    if (s1 == nullptr) {
        cudaStreamCreateWithFlags(&s1, cudaStreamNonBlocking);
        cudaStreamCreateWithFlags(&s2, cudaStreamNonBlocking);
        cudaEventCreateWithFlags(&ev_fork, cudaEventDisableTiming);
        cudaEventCreateWithFlags(&ev_join, cudaEventDisableTiming);
        cudaEventCreateWithFlags(&ev_fill, cudaEventDisableTiming);
        cudaEventCreateWithFlags(&ev_b1,   cudaEventDisableTiming);
        cudaEventCreateWithFlags(&ev_xh,   cudaEventDisableTiming);
    }

    cudaEventRecord(ev_fork, 0);

    // side stream: xh -> transposes -> join (masks are gone)
    cudaStreamWaitEvent(s2, ev_fork, 0);
    xh_kernel<<<(N_NODES * 256 / 4) / 256, 256, 0, s2>>>(x);
    cudaEventRecord(ev_xh, s2);
    {
        dim3 blk(32, 8);
        transpose2_kernel<<<dim3(16, 16, 2), blk, 0, s2>>>(W1, W2);
    }
    cudaEventRecord(ev_join, s2);

    // main stream: preproc (exact-coverage ILP-5 grids)
    count_kernel<<<125, 256>>>(ei);
    scan_kernel<<<1, 1024>>>();
    fill_kernel<<<125, 256>>>(ei);
    cudaEventRecord(ev_fill, 0);

    cudaStreamWaitEvent(0, ev_xh, 0);
    aggx_kernel<<<SPLIT_M, 128>>>(0);

    // chain B on s1 overlaps GEMM1A
    cudaStreamWaitEvent(s1, ev_fill, 0);
    cudaStreamWaitEvent(s1, ev_xh, 0);
    aggx_kernel<<<N_NODES - SPLIT_M, 128, 0, s1>>>(SPLIT_M);
    cudaStreamWaitEvent(s1, ev_join, 0);
    hgemm_kernel<512, 256, 1><<<dim3(4, 39), 256, SMEMB, s1>>>(
        p_aggx, p_w1t, p_h1, b1, dk1_0, dk1_1, N_NODES, SPLIT_M);
    cudaEventRecord(ev_b1, s1);

    cudaStreamWaitEvent(0, ev_join, 0);
    hgemm_kernel<512, 256, 1><<<dim3(4, 40), 256, SMEMB>>>(
        p_aggx, p_w1t, p_h1, b1, dk1_0, dk1_1, N_NODES, 0);

    // layer 2
    cudaStreamWaitEvent(0, ev_b1, 0);
    hgemm_kernel<256, 512, 0><<<dim3(2, 79), 256, SMEMB>>>(
        p_h1, p_w2t, p_xw2, nullptr, 0u, 0u, N_NODES, 0);
    agg2_kernel<<<N_NODES, 128>>>(p_xw2, b2, out, dk2_0, dk2_1);
}

// round 15
// speedup vs baseline: 1.1638x; 1.1638x over previous
#include <cuda_runtime.h>
#include <cuda_fp16.h>
#include <stdint.h>

#define N_NODES 10000
#define N_EDGES 160000
#define M_PAD   10112           // 79 * 128
#define SPLIT_M 5120            // 40 tiles chain A, 39 chain B
#define NBLK    40              // scan blocks: 40 x 250 = 10000

// ---------------- device scratch (no allocations allowed) ----------------
__device__ __half g_xh  [N_NODES * 256];  // x, fp16
__device__ __half g_aggx[M_PAD * 256];    // ÂX, fp16
__device__ __half g_h1  [M_PAD * 512];    // layer-1 out, fp16
__device__ __half g_xw2 [N_NODES * 256];  // h1 @ W2, fp16
__device__ __half g_w1t [512 * 256];      // W1^T, fp16
__device__ __half g_w2t [256 * 512];      // W2^T, fp16
__device__ unsigned g_mask1[160000];      // 5.12M dropout bits (layer 1)
__device__ float g_dinv[N_NODES];
__device__ int   g_cnt[N_NODES];          // zero at load; scan3 self-clears
__device__ int   g_off[N_NODES + 1];
__device__ int   g_cur[N_NODES];
__device__ int   g_csr[N_EDGES];
__device__ int   g_bsum[NBLK];
__device__ int   g_boff[NBLK];

// ---------------- PTX helpers ----------------
__device__ __forceinline__ uint32_t smem_to_u32(const void* p) {
    uint32_t a;
    asm("{ .reg .u64 t; cvta.to.shared.u64 t, %1; cvt.u32.u64 %0, t; }" : "=r"(a) : "l"(p));
    return a;
}
__device__ __forceinline__ void cp_async16(uint32_t dst, const void* src) {
    asm volatile("cp.async.cg.shared.global [%0], [%1], 16;" :: "r"(dst), "l"(src));
}
#define CP_COMMIT()  asm volatile("cp.async.commit_group;" ::: "memory")
#define CP_WAIT(n)   asm volatile("cp.async.wait_group %0;" :: "n"(n) : "memory")

__device__ __forceinline__ void mma_f16(float* d, const uint32_t* a, const uint32_t* b) {
    asm volatile(
        "mma.sync.aligned.m16n8k16.row.col.f32.f16.f16.f32 "
        "{%0,%1,%2,%3},{%4,%5,%6,%7},{%8,%9},{%0,%1,%2,%3};"
        : "+f"(d[0]), "+f"(d[1]), "+f"(d[2]), "+f"(d[3])
        : "r"(a[0]), "r"(a[1]), "r"(a[2]), "r"(a[3]), "r"(b[0]), "r"(b[1]));
}

// ---------------- threefry2x32 (JAX-compatible, validated) ----------------
#define TF_ROUND(v0, v1, r) do { (v0) += (v1); (v1) = ((v1) << (r)) | ((v1) >> (32 - (r))); (v1) ^= (v0); } while (0)
__host__ __device__ __forceinline__ void tf2x32(unsigned k0, unsigned k1,
                                                unsigned x0, unsigned x1,
                                                unsigned& o0, unsigned& o1) {
    unsigned ks0 = k0, ks1 = k1, ks2 = k0 ^ k1 ^ 0x1BD11BDAu;
    unsigned v0 = x0 + ks0, v1 = x1 + ks1;
    TF_ROUND(v0, v1, 13); TF_ROUND(v0, v1, 15); TF_ROUND(v0, v1, 26); TF_ROUND(v0, v1, 6);
    v0 += ks1; v1 += ks2 + 1u;
    TF_ROUND(v0, v1, 17); TF_ROUND(v0, v1, 29); TF_ROUND(v0, v1, 16); TF_ROUND(v0, v1, 24);
    v0 += ks2; v1 += ks0 + 2u;
    TF_ROUND(v0, v1, 13); TF_ROUND(v0, v1, 15); TF_ROUND(v0, v1, 26); TF_ROUND(v0, v1, 6);
    v0 += ks0; v1 += ks1 + 3u;
    TF_ROUND(v0, v1, 17); TF_ROUND(v0, v1, 29); TF_ROUND(v0, v1, 16); TF_ROUND(v0, v1, 24);
    v0 += ks1; v1 += ks2 + 4u;
    TF_ROUND(v0, v1, 13); TF_ROUND(v0, v1, 15); TF_ROUND(v0, v1, 26); TF_ROUND(v0, v1, 6);
    v0 += ks2; v1 += ks0 + 5u;
    o0 = v0; o1 = v1;
}
__device__ __forceinline__ bool tf_keep(unsigned k0, unsigned k1, unsigned i) {
    unsigned y0, y1;
    tf2x32(k0, k1, 0u, i, y0, y1);
    return ((y0 ^ y1) >> 31) == 0u;     // u < 0.5 (validated R10-R13)
}

// ---------------- preprocessing --------------------------------------------
// ILP-5 count: 125 blocks x 256 threads x 5 edges = exactly 160000.
__global__ void count_kernel(const void* __restrict__ ei) {
    int e0 = (blockIdx.x * blockDim.x + threadIdx.x) * 5;
    const unsigned* u = (const unsigned*)ei;
    unsigned hior = 0;
#pragma unroll
    for (int j = 0; j < 5; j++) hior |= u[2u * (unsigned)(e0 + j) + 1u];
    bool is64 = !__any_sync(0xffffffffu, hior != 0u);
    int d[5];
    if (is64) {
        const long long* p = (const long long*)ei + N_EDGES + e0;
#pragma unroll
        for (int j = 0; j < 5; j++) d[j] = (int)p[j];
    } else {
        const int* p = (const int*)ei + N_EDGES + e0;
#pragma unroll
        for (int j = 0; j < 5; j++) d[j] = p[j];
    }
#pragma unroll
    for (int j = 0; j < 5; j++) atomicAdd(&g_cnt[d[j]], 1);
}

// scan phase 1: per-block sums of 250 counts (40 blocks)
__global__ void scan1_kernel() {
    int b = blockIdx.x;
    int t = threadIdx.x;
    int c = (t < 250) ? g_cnt[b * 250 + t] : 0;
    __shared__ int wsum[8];
    int lane = t & 31, wid = t >> 5;
    int v = c;
#pragma unroll
    for (int o = 16; o > 0; o >>= 1) v += __shfl_down_sync(0xffffffffu, v, o);
    if (lane == 0) wsum[wid] = v;
    __syncthreads();
    if (t == 0) {
        int s = 0;
#pragma unroll
        for (int j = 0; j < 8; j++) s += wsum[j];
        g_bsum[b] = s;
    }
}

// scan phase 2: one warp scans the 40 block sums -> exclusive g_boff + total
__global__ void scan2_kernel() {
    int lane = threadIdx.x;   // 32 threads
    int v0 = (lane < NBLK) ? g_bsum[lane] : 0;
    int v1 = (lane + 32 < NBLK) ? g_bsum[lane + 32] : 0;
    int i0 = v0;
#pragma unroll
    for (int o = 1; o < 32; o <<= 1) {
        int x = __shfl_up_sync(0xffffffffu, i0, o);
        if (lane >= o) i0 += x;
    }
    int sum0 = __shfl_sync(0xffffffffu, i0, 31);
    int i1 = v1;
#pragma unroll
    for (int o = 1; o < 32; o <<= 1) {
        int x = __shfl_up_sync(0xffffffffu, i1, o);
        if (lane >= o) i1 += x;
    }
    int sum1 = __shfl_sync(0xffffffffu, i1, 31);
    if (lane < NBLK) g_boff[lane] = i0 - v0;
    if (lane + 32 < NBLK) g_boff[lane + 32] = sum0 + i1 - v1;
    if (lane == 0) g_off[N_NODES] = sum0 + sum1;
}

// scan phase 3: local exclusive scan + block offset; writes off/cur/dinv, clears cnt
__global__ void scan3_kernel() {
    __shared__ int wpre[8];
    int b = blockIdx.x;
    int t = threadIdx.x;
    int lane = t & 31, wid = t >> 5;
    int i = b * 250 + t;
    int c = (t < 250) ? g_cnt[i] : 0;
    int incl = c;
#pragma unroll
    for (int o = 1; o < 32; o <<= 1) {
        int x = __shfl_up_sync(0xffffffffu, incl, o);
        if (lane >= o) incl += x;
    }
    if (lane == 31) wpre[wid] = incl;
    __syncthreads();
    if (t == 0) {
        int s = 0;
#pragma unroll
        for (int j = 0; j < 8; j++) { int x = wpre[j]; wpre[j] = s; s += x; }
    }
    __syncthreads();
    if (t < 250) {
        int excl = incl - c + wpre[wid] + g_boff[b];
        g_off[i] = excl;
        g_cur[i] = excl;
        g_cnt[i] = 0;                           // self-clear for graph replay
        g_dinv[i] = rsqrtf((float)(c + 1));
    }
}

// ILP-5 fill (exact-coverage grid)
__global__ void fill_kernel(const void* __restrict__ ei) {
    int e0 = (blockIdx.x * blockDim.x + threadIdx.x) * 5;
    const unsigned* u = (const unsigned*)ei;
    unsigned hior = 0;
#pragma unroll
    for (int j = 0; j < 5; j++) hior |= u[2u * (unsigned)(e0 + j) + 1u];
    bool is64 = !__any_sync(0xffffffffu, hior != 0u);
    int s[5], d[5];
    if (is64) {
        const long long* ps = (const long long*)ei + e0;
        const long long* pd = (const long long*)ei + N_EDGES + e0;
#pragma unroll
        for (int j = 0; j < 5; j++) { s[j] = (int)ps[j]; d[j] = (int)pd[j]; }
    } else {
        const int* ps = (const int*)ei + e0;
        const int* pd = (const int*)ei + N_EDGES + e0;
#pragma unroll
        for (int j = 0; j < 5; j++) { s[j] = ps[j]; d[j] = pd[j]; }
    }
#pragma unroll
    for (int j = 0; j < 5; j++)
        g_csr[atomicAdd(&g_cur[d[j]], 1)] = s[j];
}

// x -> fp16 (vectorized)
__global__ void xh_kernel(const float* __restrict__ x) {
    int i = blockIdx.x * blockDim.x + threadIdx.x;
    float4 v = ((const float4*)x)[i];
    __half2 h0 = __floats2half2_rn(v.x, v.y);
    __half2 h1 = __floats2half2_rn(v.z, v.w);
    ((uint2*)g_xh)[i] = make_uint2(*(uint32_t*)&h0, *(uint32_t*)&h1);
}

// two transposes -> fp16
__global__ void transpose2_kernel(const float* __restrict__ W1,
                                  const float* __restrict__ W2) {
    __shared__ float tile[32][33];
    int z = blockIdx.z;
    const float* src = (z == 0) ? W1 : W2;
    __half* dst = (z == 0) ? g_w1t : g_w2t;
    int R = (z == 0) ? 256 : 512;
    int C = (z == 0) ? 512 : 256;
    if (blockIdx.x * 32 >= C || blockIdx.y * 32 >= R) return;
    int c0 = blockIdx.x * 32, r0 = blockIdx.y * 32;
#pragma unroll
    for (int i = 0; i < 32; i += 8) {
        int r = r0 + threadIdx.y + i, c = c0 + threadIdx.x;
        tile[threadIdx.y + i][threadIdx.x] = src[(size_t)r * C + c];
    }
    __syncthreads();
#pragma unroll
    for (int i = 0; i < 32; i += 8) {
        int c = c0 + threadIdx.y + i, r = r0 + threadIdx.x;
        dst[(size_t)c * R + r] = __float2half(tile[threadIdx.x][threadIdx.y + i]);
    }
}

// ILP-2 dropout bitmask for layer 1 (R13-proven)
__global__ void mask_kernel(unsigned* __restrict__ mask, unsigned k0, unsigned k1) {
    unsigned i0 = blockIdx.x * 512u + threadIdx.x;
    unsigned i1 = i0 + 256u;
    unsigned y0, y1, z0, z1;
    tf2x32(k0, k1, 0u, i0, y0, y1);
    tf2x32(k0, k1, 0u, i1, z0, z1);
    unsigned ball0 = __ballot_sync(0xffffffffu, ((y0 ^ y1) >> 31) == 0u);
    unsigned ball1 = __ballot_sync(0xffffffffu, ((z0 ^ z1) >> 31) == 0u);
    if ((threadIdx.x & 31) == 0) {
        mask[i0 >> 5] = ball0;
        mask[i1 >> 5] = ball1;
    }
}

// ---------------- fp16 tensor-core GEMM (R13 version) ------------------------
#define SROW32 36
#define S_BUF32 (256 * SROW32)

template <int N_OUT, int K_TOT, int EPI>
__global__ void __launch_bounds__(256, 2)
hgemm_kernel(const __half* __restrict__ A, const __half* __restrict__ Bt,
             __half* __restrict__ C, const float* __restrict__ bias,
             const unsigned* __restrict__ mask, int M, int m0)
{
    extern __shared__ uint32_t sm32[];
    const int tid = threadIdx.x;
    const int wid = tid >> 5, lane = tid & 31;
    const int g = lane >> 2, tig = lane & 3;
    const int wm = wid >> 1, wn = wid & 1;
    const int bm = m0 + blockIdx.y * 128;
    const int bn = blockIdx.x * 128;
    constexpr int NBK = K_TOT / 64;

    const uint32_t sbase = smem_to_u32(sm32);

    float acc[2][8][4];
#pragma unroll
    for (int mi = 0; mi < 2; mi++)
#pragma unroll
        for (int ni = 0; ni < 8; ni++)
#pragma unroll
            for (int j = 0; j < 4; j++) acc[mi][ni][j] = 0.0f;

    auto load_tile = [&](int kc, int buf) {
#pragma unroll
        for (int r = 0; r < 4; r++) {
            int chunk = r * 256 + tid;
            int row = chunk >> 3;
            int f4  = chunk & 7;
            int gr = bm + row; if (gr >= M) gr = M - 1;
            uint32_t dA = sbase + (uint32_t)(buf * S_BUF32 + row * SROW32 + f4 * 4) * 4u;
            cp_async16(dA, A + (size_t)gr * K_TOT + kc * 64 + f4 * 8);
            int gn = bn + row;
            uint32_t dB = sbase + (uint32_t)(buf * S_BUF32 + (128 + row) * SROW32 + f4 * 4) * 4u;
            cp_async16(dB, Bt + (size_t)gn * K_TOT + kc * 64 + f4 * 8);
        }
    };

    load_tile(0, 0);
    CP_COMMIT();

    for (int kc = 0; kc < NBK; kc++) {
        int buf = kc & 1;
        if (kc + 1 < NBK) {
            load_tile(kc + 1, buf ^ 1);
            CP_COMMIT();
            CP_WAIT(1);
        } else {
            CP_WAIT(0);
        }
        __syncthreads();

        const uint32_t* As = sm32 + buf * S_BUF32;
        const uint32_t* Bs = As + 128 * SROW32;
        const int rm = wm * 32;
        const int cn = wn * 64;

#pragma unroll
        for (int s = 0; s < 4; s++) {
            int k0u = s * 8;
            uint32_t af[2][4];
#pragma unroll
            for (int mi = 0; mi < 2; mi++) {
                int r0 = rm + mi * 16 + g;
                af[mi][0] = As[r0 * SROW32 + k0u + tig];
                af[mi][1] = As[(r0 + 8) * SROW32 + k0u + tig];
                af[mi][2] = As[r0 * SROW32 + k0u + 4 + tig];
                af[mi][3] = As[(r0 + 8) * SROW32 + k0u + 4 + tig];
            }
#pragma unroll
            for (int ni = 0; ni < 8; ni++) {
                int n0 = cn + ni * 8 + g;
                uint32_t bf[2];
                bf[0] = Bs[n0 * SROW32 + k0u + tig];
                bf[1] = Bs[n0 * SROW32 + k0u + 4 + tig];
                mma_f16(acc[0][ni], af[0], bf);
                mma_f16(acc[1][ni], af[1], bf);
            }
        }
        __syncthreads();
    }

#pragma unroll
    for (int mi = 0; mi < 2; mi++) {
#pragma unroll
        for (int h = 0; h < 2; h++) {
            int m = bm + wm * 32 + mi * 16 + g + h * 8;
            if (m >= M) continue;
#pragma unroll
            for (int ni = 0; ni < 8; ni++) {
                int n0 = bn + wn * 64 + ni * 8 + tig * 2;
                float v0 = acc[mi][ni][h * 2 + 0];
                float v1 = acc[mi][ni][h * 2 + 1];
                if (EPI == 0) {
                    *(__half2*)(C + (size_t)m * N_OUT + n0) = __floats2half2_rn(v0, v1);
                } else {
                    float r0v = fmaxf(v0 + bias[n0], 0.0f);
                    float r1v = fmaxf(v1 + bias[n0 + 1], 0.0f);
                    unsigned idx = (unsigned)m * (unsigned)N_OUT + (unsigned)n0;
                    unsigned w = mask[idx >> 5];
                    r0v = ((w >> (idx & 31)) & 1u) ? r0v * 2.0f : 0.0f;
                    r1v = ((w >> ((idx + 1) & 31)) & 1u) ? r1v * 2.0f : 0.0f;
                    *(__half2*)(C + (size_t)m * N_OUT + n0) = __floats2half2_rn(r0v, r1v);
                }
            }
        }
    }
}

// ---------------- aggregations (half2 gathers) -------------------------------
__global__ void aggx_kernel(int base) {
    int n = base + blockIdx.x, c2 = threadIdx.x;
    float dn = g_dinv[n];
    float2 hv = __half22float2(((const __half2*)(g_xh + (size_t)n * 256))[c2]);
    float a0 = dn * hv.x, a1 = dn * hv.y;
    int k0 = g_off[n], k1 = g_off[n + 1];
    for (int k = k0; k < k1; k++) {
        int s = g_csr[k];
        float ds = g_dinv[s];
        float2 sv = __half22float2(((const __half2*)(g_xh + (size_t)s * 256))[c2]);
        a0 += ds * sv.x;
        a1 += ds * sv.y;
    }
    ((__half2*)(g_aggx + (size_t)n * 256))[c2] = __floats2half2_rn(a0 * dn, a1 * dn);
}

// agg2: gather + bias + relu + INLINE threefry dropout (R5-R7 proven)
__global__ void agg2_kernel(const __half* __restrict__ xw,
                            const float* __restrict__ bias,
                            float* __restrict__ out,
                            unsigned dk0, unsigned dk1) {
    int n = blockIdx.x, c2 = threadIdx.x;
    float dn = g_dinv[n];
    float2 hv = __half22float2(((const __half2*)(xw + (size_t)n * 256))[c2]);
    float a0 = dn * hv.x, a1 = dn * hv.y;
    int k0 = g_off[n], k1 = g_off[n + 1];
    for (int k = k0; k < k1; k++) {
        int s = g_csr[k];
        float ds = g_dinv[s];
        float2 sv = __half22float2(((const __half2*)(xw + (size_t)s * 256))[c2]);
        a0 += ds * sv.x;
        a1 += ds * sv.y;
    }
    int c = c2 * 2;
    float v0 = fmaxf(a0 * dn + bias[c], 0.0f);
    float v1 = fmaxf(a1 * dn + bias[c + 1], 0.0f);
    unsigned i = (unsigned)(n * 256 + c);
    out[i]     = tf_keep(dk0, dk1, i)      ? v0 * 2.0f : 0.0f;
    out[i + 1] = tf_keep(dk0, dk1, i + 1u) ? v1 * 2.0f : 0.0f;
}

// ---------------- launch (R13 topology; scan split; mask2 inlined) -----------
extern "C" void kernel_launch(void* const* d_in, const int* in_sizes, int n_in,
                              void* d_out, int out_size)
{
    const float* x  = (const float*)d_in[0];
    const void*  ei = d_in[1];
    const float* W1 = (const float*)d_in[2];
    const float* b1 = (const float*)d_in[3];
    const float* W2 = (const float*)d_in[4];
    const float* b2 = (const float*)d_in[5];
    float* out = (float*)d_out;

    __half *p_aggx, *p_h1, *p_xw2, *p_w1t, *p_w2t;
    unsigned* p_m1;
    cudaGetSymbolAddress((void**)&p_aggx, g_aggx);
    cudaGetSymbolAddress((void**)&p_h1,   g_h1);
    cudaGetSymbolAddress((void**)&p_xw2,  g_xw2);
    cudaGetSymbolAddress((void**)&p_w1t,  g_w1t);
    cudaGetSymbolAddress((void**)&p_w2t,  g_w2t);
    cudaGetSymbolAddress((void**)&p_m1,   g_mask1);

    constexpr int SMEMB = 2 * S_BUF32 * 4;
    cudaFuncSetAttribute(hgemm_kernel<512, 256, 1>,
                         cudaFuncAttributeMaxDynamicSharedMemorySize, SMEMB);
    cudaFuncSetAttribute(hgemm_kernel<256, 512, 0>,
                         cudaFuncAttributeMaxDynamicSharedMemorySize, SMEMB);

    unsigned dk1_0, dk1_1, dk2_0, dk2_1;
    tf2x32(0u, 42u, 0u, 0u, dk1_0, dk1_1);
    tf2x32(0u, 42u, 0u, 1u, dk2_0, dk2_1);

    static cudaStream_t s1 = nullptr, s2 = nullptr;
    static cudaEvent_t ev_fork = nullptr, ev_join = nullptr, ev_fill = nullptr,
                       ev_b1 = nullptr, ev_xh = nullptr;
    if (s1 == nullptr) {
        cudaStreamCreateWithFlags(&s1, cudaStreamNonBlocking);
        cudaStreamCreateWithFlags(&s2, cudaStreamNonBlocking);
        cudaEventCreateWithFlags(&ev_fork, cudaEventDisableTiming);
        cudaEventCreateWithFlags(&ev_join, cudaEventDisableTiming);
        cudaEventCreateWithFlags(&ev_fill, cudaEventDisableTiming);
        cudaEventCreateWithFlags(&ev_b1,   cudaEventDisableTiming);
        cudaEventCreateWithFlags(&ev_xh,   cudaEventDisableTiming);
    }

    cudaEventRecord(ev_fork, 0);

    // side stream: xh -> transposes -> mask1 (mask2 is inlined in agg2)
    cudaStreamWaitEvent(s2, ev_fork, 0);
    xh_kernel<<<(N_NODES * 256 / 4) / 256, 256, 0, s2>>>(x);
    cudaEventRecord(ev_xh, s2);
    {
        dim3 blk(32, 8);
        transpose2_kernel<<<dim3(16, 16, 2), blk, 0, s2>>>(W1, W2);
    }
    mask_kernel<<<10000, 256, 0, s2>>>(p_m1, dk1_0, dk1_1);   // ILP-2
    cudaEventRecord(ev_join, s2);

    // main stream: preproc with multi-SM scan
    count_kernel<<<125, 256>>>(ei);
    scan1_kernel<<<NBLK, 256>>>();
    scan2_kernel<<<1, 32>>>();
    scan3_kernel<<<NBLK, 256>>>();
    fill_kernel<<<125, 256>>>(ei);
    cudaEventRecord(ev_fill, 0);

    cudaStreamWaitEvent(0, ev_xh, 0);
    aggx_kernel<<<SPLIT_M, 128>>>(0);

    // chain B on s1 overlaps GEMM1A
    cudaStreamWaitEvent(s1, ev_fill, 0);
    cudaStreamWaitEvent(s1, ev_xh, 0);
    aggx_kernel<<<N_NODES - SPLIT_M, 128, 0, s1>>>(SPLIT_M);
    cudaStreamWaitEvent(s1, ev_join, 0);
    hgemm_kernel<512, 256, 1><<<dim3(4, 39), 256, SMEMB, s1>>>(
        p_aggx, p_w1t, p_h1, b1, p_m1, N_NODES, SPLIT_M);
    cudaEventRecord(ev_b1, s1);

    cudaStreamWaitEvent(0, ev_join, 0);
    hgemm_kernel<512, 256, 1><<<dim3(4, 40), 256, SMEMB>>>(
        p_aggx, p_w1t, p_h1, b1, p_m1, N_NODES, 0);

    // layer 2
    cudaStreamWaitEvent(0, ev_b1, 0);
    hgemm_kernel<256, 512, 0><<<dim3(2, 79), 256, SMEMB>>>(
        p_h1, p_w2t, p_xw2, nullptr, nullptr, N_NODES, 0);
    agg2_kernel<<<N_NODES, 128>>>(p_xw2, b2, out, dk2_0, dk2_1);
}

// round 16
// speedup vs baseline: 1.2890x; 1.1076x over previous
#include <cuda_runtime.h>
#include <cuda_fp16.h>
#include <stdint.h>

#define N_NODES 10000
#define N_EDGES 160000
#define M_PAD   10112           // 79 * 128
#define SPLIT_M 5120            // 40 tiles chain A, 39 chain B
#define PRE_BLK 125             // preproc blocks: 125 x 256 x 5 = 160000 edges

// ---------------- device scratch (no allocations allowed) ----------------
__device__ __half g_xh  [N_NODES * 256];  // x, fp16
__device__ __half g_aggx[M_PAD * 256];    // ÂX, fp16
__device__ __half g_h1  [M_PAD * 512];    // layer-1 out, fp16
__device__ __half g_xw2 [N_NODES * 256];  // h1 @ W2, fp16
__device__ __half g_w1t [512 * 256];      // W1^T, fp16
__device__ __half g_w2t [256 * 512];      // W2^T, fp16
__device__ unsigned g_mask1[160000];      // 5.12M dropout bits (layer 1)
__device__ float g_dinv[N_NODES];
__device__ int   g_cnt[N_NODES];          // zero at load; preproc self-clears
__device__ int   g_off[N_NODES + 1];
__device__ int   g_cur[N_NODES];
__device__ int   g_csr[N_EDGES];
__device__ int   g_bsum[40];
__device__ unsigned g_arrive = 0;         // barrier arrive counter (self-resets)
__device__ unsigned g_gen = 0;            // barrier generation (monotonic)

// ---------------- PTX helpers ----------------
__device__ __forceinline__ uint32_t smem_to_u32(const void* p) {
    uint32_t a;
    asm("{ .reg .u64 t; cvta.to.shared.u64 t, %1; cvt.u32.u64 %0, t; }" : "=r"(a) : "l"(p));
    return a;
}
__device__ __forceinline__ void cp_async16(uint32_t dst, const void* src) {
    asm volatile("cp.async.cg.shared.global [%0], [%1], 16;" :: "r"(dst), "l"(src));
}
#define CP_COMMIT()  asm volatile("cp.async.commit_group;" ::: "memory")
#define CP_WAIT(n)   asm volatile("cp.async.wait_group %0;" :: "n"(n) : "memory")

__device__ __forceinline__ void mma_f16(float* d, const uint32_t* a, const uint32_t* b) {
    asm volatile(
        "mma.sync.aligned.m16n8k16.row.col.f32.f16.f16.f32 "
        "{%0,%1,%2,%3},{%4,%5,%6,%7},{%8,%9},{%0,%1,%2,%3};"
        : "+f"(d[0]), "+f"(d[1]), "+f"(d[2]), "+f"(d[3])
        : "r"(a[0]), "r"(a[1]), "r"(a[2]), "r"(a[3]), "r"(b[0]), "r"(b[1]));
}

// ---------------- threefry2x32 (JAX-compatible, validated) ----------------
#define TF_ROUND(v0, v1, r) do { (v0) += (v1); (v1) = ((v1) << (r)) | ((v1) >> (32 - (r))); (v1) ^= (v0); } while (0)
__host__ __device__ __forceinline__ void tf2x32(unsigned k0, unsigned k1,
                                                unsigned x0, unsigned x1,
                                                unsigned& o0, unsigned& o1) {
    unsigned ks0 = k0, ks1 = k1, ks2 = k0 ^ k1 ^ 0x1BD11BDAu;
    unsigned v0 = x0 + ks0, v1 = x1 + ks1;
    TF_ROUND(v0, v1, 13); TF_ROUND(v0, v1, 15); TF_ROUND(v0, v1, 26); TF_ROUND(v0, v1, 6);
    v0 += ks1; v1 += ks2 + 1u;
    TF_ROUND(v0, v1, 17); TF_ROUND(v0, v1, 29); TF_ROUND(v0, v1, 16); TF_ROUND(v0, v1, 24);
    v0 += ks2; v1 += ks0 + 2u;
    TF_ROUND(v0, v1, 13); TF_ROUND(v0, v1, 15); TF_ROUND(v0, v1, 26); TF_ROUND(v0, v1, 6);
    v0 += ks0; v1 += ks1 + 3u;
    TF_ROUND(v0, v1, 17); TF_ROUND(v0, v1, 29); TF_ROUND(v0, v1, 16); TF_ROUND(v0, v1, 24);
    v0 += ks1; v1 += ks2 + 4u;
    TF_ROUND(v0, v1, 13); TF_ROUND(v0, v1, 15); TF_ROUND(v0, v1, 26); TF_ROUND(v0, v1, 6);
    v0 += ks2; v1 += ks0 + 5u;
    o0 = v0; o1 = v1;
}
__device__ __forceinline__ bool tf_keep(unsigned k0, unsigned k1, unsigned i) {
    unsigned y0, y1;
    tf2x32(k0, k1, 0u, i, y0, y1);
    return ((y0 ^ y1) >> 31) == 0u;     // u < 0.5 (validated R10-R15)
}

// ---------------- fused preprocessing: count | scan | fill (1 kernel) --------
// Sense-reversal grid barrier: arrive counter self-resets; spinners wait on the
// monotonic generation counter (base re-read every launch -> graph-replay safe).
__device__ __forceinline__ void grid_bar(unsigned target_gen, int nblk) {
    __syncthreads();
    if (threadIdx.x == 0) {
        __threadfence();
        unsigned old = atomicAdd(&g_arrive, 1u);
        if (old == (unsigned)(nblk - 1)) {
            atomicExch(&g_arrive, 0u);
            __threadfence();
            atomicAdd(&g_gen, 1u);
        } else {
            while (atomicAdd(&g_gen, 0u) < target_gen) { }
        }
    }
    __syncthreads();
}

__global__ void __launch_bounds__(256) preproc_kernel(const void* __restrict__ ei) {
    const int blk = blockIdx.x, tid = threadIdx.x;
    const int lane = tid & 31, wrp = tid >> 5;
    __shared__ unsigned s_base;
    __shared__ int wpre[8];
    __shared__ int s_boff;
    if (tid == 0) s_base = atomicAdd(&g_gen, 0u);
    __syncthreads();
    const unsigned base = s_base;

    // dtype detection (warp-local, in-bounds for both dtypes)
    int e0 = (blk * 256 + tid) * 5;
    const unsigned* u = (const unsigned*)ei;
    unsigned hior = 0;
#pragma unroll
    for (int j = 0; j < 5; j++) hior |= u[2u * (unsigned)(e0 + j) + 1u];
    bool is64 = !__any_sync(0xffffffffu, hior != 0u);

    // ---- phase 1: degree count (all 125 blocks, ILP-5 exact coverage) ----
    {
        int d[5];
        if (is64) {
            const long long* p = (const long long*)ei + N_EDGES + e0;
#pragma unroll
            for (int j = 0; j < 5; j++) d[j] = (int)p[j];
        } else {
            const int* p = (const int*)ei + N_EDGES + e0;
#pragma unroll
            for (int j = 0; j < 5; j++) d[j] = p[j];
        }
#pragma unroll
        for (int j = 0; j < 5; j++) atomicAdd(&g_cnt[d[j]], 1);
    }
    grid_bar(base + 1, PRE_BLK);

    // ---- phase 2: blocks 0-39 block-local scan + publish bsum ----
    int c = 0, lexcl = 0;
    if (blk < 40) {
        int i = blk * 250 + tid;
        c = (tid < 250) ? g_cnt[i] : 0;
        int incl = c;
#pragma unroll
        for (int o = 1; o < 32; o <<= 1) {
            int x = __shfl_up_sync(0xffffffffu, incl, o);
            if (lane >= o) incl += x;
        }
        if (lane == 31) wpre[wrp] = incl;
        __syncthreads();
        if (tid == 0) {
            int s = 0;
#pragma unroll
            for (int j = 0; j < 8; j++) { int x = wpre[j]; wpre[j] = s; s += x; }
            g_bsum[blk] = s;
        }
        __syncthreads();
        lexcl = incl - c + wpre[wrp];
    }
    grid_bar(base + 2, PRE_BLK);

    // ---- phase 3: blocks 0-39 add block offset, write off/cur/dinv, clear cnt
    if (blk < 40) {
        if (tid < 32) {
            int v0 = (lane < 40) ? g_bsum[lane] : 0;
            int v1 = (lane < 8)  ? g_bsum[lane + 32] : 0;
            int i0 = v0;
#pragma unroll
            for (int o = 1; o < 32; o <<= 1) {
                int x = __shfl_up_sync(0xffffffffu, i0, o);
                if (lane >= o) i0 += x;
            }
            int sum0 = __shfl_sync(0xffffffffu, i0, 31);
            int i1 = v1;
#pragma unroll
            for (int o = 1; o < 32; o <<= 1) {
                int x = __shfl_up_sync(0xffffffffu, i1, o);
                if (lane >= o) i1 += x;
            }
            int sum1 = __shfl_sync(0xffffffffu, i1, 31);
            int e0v = i0 - v0;
            int e1v = sum0 + i1 - v1;
            int pick = (blk < 32) ? __shfl_sync(0xffffffffu, e0v, blk)
                                  : __shfl_sync(0xffffffffu, e1v, blk - 32);
            if (lane == 0) s_boff = pick;
            if (blk == 0 && lane == 0) g_off[N_NODES] = sum0 + sum1;
        }
        __syncthreads();
        if (tid < 250) {
            int i = blk * 250 + tid;
            int excl = lexcl + s_boff;
            g_off[i] = excl;
            g_cur[i] = excl;
            g_cnt[i] = 0;                       // self-clear for graph replay
            g_dinv[i] = rsqrtf((float)(c + 1));
        }
    }
    grid_bar(base + 3, PRE_BLK);

    // ---- phase 4: CSR fill (all 125 blocks) ----
    {
        int s[5], d[5];
        if (is64) {
            const long long* ps = (const long long*)ei + e0;
            const long long* pd = (const long long*)ei + N_EDGES + e0;
#pragma unroll
            for (int j = 0; j < 5; j++) { s[j] = (int)ps[j]; d[j] = (int)pd[j]; }
        } else {
            const int* ps = (const int*)ei + e0;
            const int* pd = (const int*)ei + N_EDGES + e0;
#pragma unroll
            for (int j = 0; j < 5; j++) { s[j] = ps[j]; d[j] = pd[j]; }
        }
#pragma unroll
        for (int j = 0; j < 5; j++)
            g_csr[atomicAdd(&g_cur[d[j]], 1)] = s[j];
    }
}

// x -> fp16 (vectorized)
__global__ void xh_kernel(const float* __restrict__ x) {
    int i = blockIdx.x * blockDim.x + threadIdx.x;
    float4 v = ((const float4*)x)[i];
    __half2 h0 = __floats2half2_rn(v.x, v.y);
    __half2 h1 = __floats2half2_rn(v.z, v.w);
    ((uint2*)g_xh)[i] = make_uint2(*(uint32_t*)&h0, *(uint32_t*)&h1);
}

// two transposes -> fp16
__global__ void transpose2_kernel(const float* __restrict__ W1,
                                  const float* __restrict__ W2) {
    __shared__ float tile[32][33];
    int z = blockIdx.z;
    const float* src = (z == 0) ? W1 : W2;
    __half* dst = (z == 0) ? g_w1t : g_w2t;
    int R = (z == 0) ? 256 : 512;
    int C = (z == 0) ? 512 : 256;
    if (blockIdx.x * 32 >= C || blockIdx.y * 32 >= R) return;
    int c0 = blockIdx.x * 32, r0 = blockIdx.y * 32;
#pragma unroll
    for (int i = 0; i < 32; i += 8) {
        int r = r0 + threadIdx.y + i, c = c0 + threadIdx.x;
        tile[threadIdx.y + i][threadIdx.x] = src[(size_t)r * C + c];
    }
    __syncthreads();
#pragma unroll
    for (int i = 0; i < 32; i += 8) {
        int c = c0 + threadIdx.y + i, r = r0 + threadIdx.x;
        dst[(size_t)c * R + r] = __float2half(tile[threadIdx.x][threadIdx.y + i]);
    }
}

// ILP-2 dropout bitmask for layer 1 (R13-proven)
__global__ void mask_kernel(unsigned* __restrict__ mask, unsigned k0, unsigned k1) {
    unsigned i0 = blockIdx.x * 512u + threadIdx.x;
    unsigned i1 = i0 + 256u;
    unsigned y0, y1, z0, z1;
    tf2x32(k0, k1, 0u, i0, y0, y1);
    tf2x32(k0, k1, 0u, i1, z0, z1);
    unsigned ball0 = __ballot_sync(0xffffffffu, ((y0 ^ y1) >> 31) == 0u);
    unsigned ball1 = __ballot_sync(0xffffffffu, ((z0 ^ z1) >> 31) == 0u);
    if ((threadIdx.x & 31) == 0) {
        mask[i0 >> 5] = ball0;
        mask[i1 >> 5] = ball1;
    }
}

// ---------------- fp16 tensor-core GEMM1 (BM=128, mask epilogue) -------------
#define SROW32 36
#define S_BUF32 (256 * SROW32)

__global__ void __launch_bounds__(256, 2)
hgemm1_kernel(const __half* __restrict__ A, const __half* __restrict__ Bt,
              __half* __restrict__ C, const float* __restrict__ bias,
              const unsigned* __restrict__ mask, int M, int m0)
{
    extern __shared__ uint32_t sm32[];
    constexpr int N_OUT = 512, K_TOT = 256, NBK = K_TOT / 64;
    const int tid = threadIdx.x;
    const int wid = tid >> 5, lane = tid & 31;
    const int g = lane >> 2, tig = lane & 3;
    const int wm = wid >> 1, wn = wid & 1;
    const int bm = m0 + blockIdx.y * 128;
    const int bn = blockIdx.x * 128;
    const uint32_t sbase = smem_to_u32(sm32);

    float acc[2][8][4];
#pragma unroll
    for (int mi = 0; mi < 2; mi++)
#pragma unroll
        for (int ni = 0; ni < 8; ni++)
#pragma unroll
            for (int j = 0; j < 4; j++) acc[mi][ni][j] = 0.0f;

    auto load_tile = [&](int kc, int buf) {
#pragma unroll
        for (int r = 0; r < 4; r++) {
            int chunk = r * 256 + tid;
            int row = chunk >> 3;
            int f4  = chunk & 7;
            int gr = bm + row; if (gr >= M) gr = M - 1;
            uint32_t dA = sbase + (uint32_t)(buf * S_BUF32 + row * SROW32 + f4 * 4) * 4u;
            cp_async16(dA, A + (size_t)gr * K_TOT + kc * 64 + f4 * 8);
            int gn = bn + row;
            uint32_t dB = sbase + (uint32_t)(buf * S_BUF32 + (128 + row) * SROW32 + f4 * 4) * 4u;
            cp_async16(dB, Bt + (size_t)gn * K_TOT + kc * 64 + f4 * 8);
        }
    };

    load_tile(0, 0);
    CP_COMMIT();

    for (int kc = 0; kc < NBK; kc++) {
        int buf = kc & 1;
        if (kc + 1 < NBK) {
            load_tile(kc + 1, buf ^ 1);
            CP_COMMIT();
            CP_WAIT(1);
        } else {
            CP_WAIT(0);
        }
        __syncthreads();

        const uint32_t* As = sm32 + buf * S_BUF32;
        const uint32_t* Bs = As + 128 * SROW32;
        const int rm = wm * 32;
        const int cn = wn * 64;

#pragma unroll
        for (int s = 0; s < 4; s++) {
            int k0u = s * 8;
            uint32_t af[2][4];
#pragma unroll
            for (int mi = 0; mi < 2; mi++) {
                int r0 = rm + mi * 16 + g;
                af[mi][0] = As[r0 * SROW32 + k0u + tig];
                af[mi][1] = As[(r0 + 8) * SROW32 + k0u + tig];
                af[mi][2] = As[r0 * SROW32 + k0u + 4 + tig];
                af[mi][3] = As[(r0 + 8) * SROW32 + k0u + 4 + tig];
            }
#pragma unroll
            for (int ni = 0; ni < 8; ni++) {
                int n0 = cn + ni * 8 + g;
                uint32_t bf[2];
                bf[0] = Bs[n0 * SROW32 + k0u + tig];
                bf[1] = Bs[n0 * SROW32 + k0u + 4 + tig];
                mma_f16(acc[0][ni], af[0], bf);
                mma_f16(acc[1][ni], af[1], bf);
            }
        }
        __syncthreads();
    }

#pragma unroll
    for (int mi = 0; mi < 2; mi++) {
#pragma unroll
        for (int h = 0; h < 2; h++) {
            int m = bm + wm * 32 + mi * 16 + g + h * 8;
            if (m >= M) continue;
#pragma unroll
            for (int ni = 0; ni < 8; ni++) {
                int n0 = bn + wn * 64 + ni * 8 + tig * 2;
                float v0 = acc[mi][ni][h * 2 + 0];
                float v1 = acc[mi][ni][h * 2 + 1];
                float r0v = fmaxf(v0 + bias[n0], 0.0f);
                float r1v = fmaxf(v1 + bias[n0 + 1], 0.0f);
                unsigned idx = (unsigned)m * (unsigned)N_OUT + (unsigned)n0;
                unsigned w = mask[idx >> 5];
                r0v = ((w >> (idx & 31)) & 1u) ? r0v * 2.0f : 0.0f;
                r1v = ((w >> ((idx + 1) & 31)) & 1u) ? r1v * 2.0f : 0.0f;
                *(__half2*)(C + (size_t)m * N_OUT + n0) = __floats2half2_rn(r0v, r1v);
            }
        }
    }
}

// ---------------- fp16 tensor-core GEMM2 (BM=64 -> 316 CTAs, full chip) ------
#define S2_BUF (192 * SROW32)    // 64 A rows + 128 B rows

__global__ void __launch_bounds__(256, 2)
hgemm2_kernel(const __half* __restrict__ A, const __half* __restrict__ Bt,
              __half* __restrict__ C, int M)
{
    extern __shared__ uint32_t sm32[];
    constexpr int N_OUT = 256, K_TOT = 512, NBK = K_TOT / 64;
    const int tid = threadIdx.x;
    const int wid = tid >> 5, lane = tid & 31;
    const int g = lane >> 2, tig = lane & 3;
    const int wm = wid >> 2, wn = wid & 3;       // 2(m) x 4(n) warps
    const int bm = blockIdx.y * 64;
    const int bn = blockIdx.x * 128;
    const uint32_t sbase = smem_to_u32(sm32);

    float acc[2][4][4];
#pragma unroll
    for (int mi = 0; mi < 2; mi++)
#pragma unroll
        for (int ni = 0; ni < 4; ni++)
#pragma unroll
            for (int j = 0; j < 4; j++) acc[mi][ni][j] = 0.0f;

    auto load_tile = [&](int kc, int buf) {
        // A: 64 rows x 8 chunks = 512
#pragma unroll
        for (int r = 0; r < 2; r++) {
            int chunk = r * 256 + tid;
            int row = chunk >> 3;
            int f4  = chunk & 7;
            int gr = bm + row; if (gr >= M) gr = M - 1;
            uint32_t dA = sbase + (uint32_t)(buf * S2_BUF + row * SROW32 + f4 * 4) * 4u;
            cp_async16(dA, A + (size_t)gr * K_TOT + kc * 64 + f4 * 8);
        }
        // B: 128 rows x 8 chunks = 1024
#pragma unroll
        for (int r = 0; r < 4; r++) {
            int chunk = r * 256 + tid;
            int row = chunk >> 3;
            int f4  = chunk & 7;
            int gn = bn + row;
            uint32_t dB = sbase + (uint32_t)(buf * S2_BUF + (64 + row) * SROW32 + f4 * 4) * 4u;
            cp_async16(dB, Bt + (size_t)gn * K_TOT + kc * 64 + f4 * 8);
        }
    };

    load_tile(0, 0);
    CP_COMMIT();

    for (int kc = 0; kc < NBK; kc++) {
        int buf = kc & 1;
        if (kc + 1 < NBK) {
            load_tile(kc + 1, buf ^ 1);
            CP_COMMIT();
            CP_WAIT(1);
        } else {
            CP_WAIT(0);
        }
        __syncthreads();

        const uint32_t* As = sm32 + buf * S2_BUF;
        const uint32_t* Bs = As + 64 * SROW32;
        const int rm = wm * 32;
        const int cn = wn * 32;

#pragma unroll
        for (int s = 0; s < 4; s++) {
            int k0u = s * 8;
            uint32_t af[2][4];
#pragma unroll
            for (int mi = 0; mi < 2; mi++) {
                int r0 = rm + mi * 16 + g;
                af[mi][0] = As[r0 * SROW32 + k0u + tig];
                af[mi][1] = As[(r0 + 8) * SROW32 + k0u + tig];
                af[mi][2] = As[r0 * SROW32 + k0u + 4 + tig];
                af[mi][3] = As[(r0 + 8) * SROW32 + k0u + 4 + tig];
            }
#pragma unroll
            for (int ni = 0; ni < 4; ni++) {
                int n0 = cn + ni * 8 + g;
                uint32_t bf[2];
                bf[0] = Bs[n0 * SROW32 + k0u + tig];
                bf[1] = Bs[n0 * SROW32 + k0u + 4 + tig];
                mma_f16(acc[0][ni], af[0], bf);
                mma_f16(acc[1][ni], af[1], bf);
            }
        }
        __syncthreads();
    }

#pragma unroll
    for (int mi = 0; mi < 2; mi++) {
#pragma unroll
        for (int h = 0; h < 2; h++) {
            int m = bm + wm * 32 + mi * 16 + g + h * 8;
            if (m >= M) continue;
#pragma unroll
            for (int ni = 0; ni < 4; ni++) {
                int n0 = bn + wn * 32 + ni * 8 + tig * 2;
                *(__half2*)(C + (size_t)m * N_OUT + n0) =
                    __floats2half2_rn(acc[mi][ni][h * 2 + 0], acc[mi][ni][h * 2 + 1]);
            }
        }
    }
}

// ---------------- aggregations (half2 gathers) -------------------------------
__global__ void aggx_kernel(int base) {
    int n = base + blockIdx.x, c2 = threadIdx.x;
    float dn = g_dinv[n];
    float2 hv = __half22float2(((const __half2*)(g_xh + (size_t)n * 256))[c2]);
    float a0 = dn * hv.x, a1 = dn * hv.y;
    int k0 = g_off[n], k1 = g_off[n + 1];
    for (int k = k0; k < k1; k++) {
        int s = g_csr[k];
        float ds = g_dinv[s];
        float2 sv = __half22float2(((const __half2*)(g_xh + (size_t)s * 256))[c2]);
        a0 += ds * sv.x;
        a1 += ds * sv.y;
    }
    ((__half2*)(g_aggx + (size_t)n * 256))[c2] = __floats2half2_rn(a0 * dn, a1 * dn);
}

// agg2: gather + bias + relu + INLINE threefry dropout (R15-proven)
__global__ void agg2_kernel(const __half* __restrict__ xw,
                            const float* __restrict__ bias,
                            float* __restrict__ out,
                            unsigned dk0, unsigned dk1) {
    int n = blockIdx.x, c2 = threadIdx.x;
    float dn = g_dinv[n];
    float2 hv = __half22float2(((const __half2*)(xw + (size_t)n * 256))[c2]);
    float a0 = dn * hv.x, a1 = dn * hv.y;
    int k0 = g_off[n], k1 = g_off[n + 1];
    for (int k = k0; k < k1; k++) {
        int s = g_csr[k];
        float ds = g_dinv[s];
        float2 sv = __half22float2(((const __half2*)(xw + (size_t)s * 256))[c2]);
        a0 += ds * sv.x;
        a1 += ds * sv.y;
    }
    int c = c2 * 2;
    float v0 = fmaxf(a0 * dn + bias[c], 0.0f);
    float v1 = fmaxf(a1 * dn + bias[c + 1], 0.0f);
    unsigned i = (unsigned)(n * 256 + c);
    out[i]     = tf_keep(dk0, dk1, i)      ? v0 * 2.0f : 0.0f;
    out[i + 1] = tf_keep(dk0, dk1, i + 1u) ? v1 * 2.0f : 0.0f;
}

// ---------------- launch (R15 topology; fused preproc; BM=64 GEMM2) ----------
extern "C" void kernel_launch(void* const* d_in, const int* in_sizes, int n_in,
                              void* d_out, int out_size)
{
    const float* x  = (const float*)d_in[0];
    const void*  ei = d_in[1];
    const float* W1 = (const float*)d_in[2];
    const float* b1 = (const float*)d_in[3];
    const float* W2 = (const float*)d_in[4];
    const float* b2 = (const float*)d_in[5];
    float* out = (float*)d_out;

    __half *p_aggx, *p_h1, *p_xw2, *p_w1t, *p_w2t;
    unsigned* p_m1;
    cudaGetSymbolAddress((void**)&p_aggx, g_aggx);
    cudaGetSymbolAddress((void**)&p_h1,   g_h1);
    cudaGetSymbolAddress((void**)&p_xw2,  g_xw2);
    cudaGetSymbolAddress((void**)&p_w1t,  g_w1t);
    cudaGetSymbolAddress((void**)&p_w2t,  g_w2t);
    cudaGetSymbolAddress((void**)&p_m1,   g_mask1);

    constexpr int SMEMB1 = 2 * S_BUF32 * 4;   // 73,728 B
    constexpr int SMEMB2 = 2 * S2_BUF * 4;    // 55,296 B
    cudaFuncSetAttribute(hgemm1_kernel,
                         cudaFuncAttributeMaxDynamicSharedMemorySize, SMEMB1);
    cudaFuncSetAttribute(hgemm2_kernel,
                         cudaFuncAttributeMaxDynamicSharedMemorySize, SMEMB2);

    unsigned dk1_0, dk1_1, dk2_0, dk2_1;
    tf2x32(0u, 42u, 0u, 0u, dk1_0, dk1_1);
    tf2x32(0u, 42u, 0u, 1u, dk2_0, dk2_1);

    static cudaStream_t s1 = nullptr, s2 = nullptr;
    static cudaEvent_t ev_fork = nullptr, ev_join = nullptr, ev_fill = nullptr,
                       ev_b1 = nullptr, ev_xh = nullptr;
    if (s1 == nullptr) {
        cudaStreamCreateWithFlags(&s1, cudaStreamNonBlocking);
        cudaStreamCreateWithFlags(&s2, cudaStreamNonBlocking);
        cudaEventCreateWithFlags(&ev_fork, cudaEventDisableTiming);
        cudaEventCreateWithFlags(&ev_join, cudaEventDisableTiming);
        cudaEventCreateWithFlags(&ev_fill, cudaEventDisableTiming);
        cudaEventCreateWithFlags(&ev_b1,   cudaEventDisableTiming);
        cudaEventCreateWithFlags(&ev_xh,   cudaEventDisableTiming);
    }

    cudaEventRecord(ev_fork, 0);

    // side stream: xh -> transposes -> mask1
    cudaStreamWaitEvent(s2, ev_fork, 0);
    xh_kernel<<<(N_NODES * 256 / 4) / 256, 256, 0, s2>>>(x);
    cudaEventRecord(ev_xh, s2);
    {
        dim3 blk(32, 8);
        transpose2_kernel<<<dim3(16, 16, 2), blk, 0, s2>>>(W1, W2);
    }
    mask_kernel<<<10000, 256, 0, s2>>>(p_m1, dk1_0, dk1_1);   // ILP-2
    cudaEventRecord(ev_join, s2);

    // main stream: fused preproc (count | scan | fill) in ONE kernel
    preproc_kernel<<<PRE_BLK, 256>>>(ei);
    cudaEventRecord(ev_fill, 0);

    cudaStreamWaitEvent(0, ev_xh, 0);
    aggx_kernel<<<SPLIT_M, 128>>>(0);

    // chain B on s1 overlaps GEMM1A
    cudaStreamWaitEvent(s1, ev_fill, 0);
    cudaStreamWaitEvent(s1, ev_xh, 0);
    aggx_kernel<<<N_NODES - SPLIT_M, 128, 0, s1>>>(SPLIT_M);
    cudaStreamWaitEvent(s1, ev_join, 0);
    hgemm1_kernel<<<dim3(4, 39), 256, SMEMB1, s1>>>(
        p_aggx, p_w1t, p_h1, b1, p_m1, N_NODES, SPLIT_M);
    cudaEventRecord(ev_b1, s1);

    cudaStreamWaitEvent(0, ev_join, 0);
    hgemm1_kernel<<<dim3(4, 40), 256, SMEMB1>>>(
        p_aggx, p_w1t, p_h1, b1, p_m1, N_NODES, 0);

    // layer 2: BM=64 GEMM (316 CTAs -> full chip), then aggregate
    cudaStreamWaitEvent(0, ev_b1, 0);
    hgemm2_kernel<<<dim3(2, 158), 256, SMEMB2>>>(p_h1, p_w2t, p_xw2, N_NODES);
    agg2_kernel<<<N_NODES, 128>>>(p_xw2, b2, out, dk2_0, dk2_1);
}